// round 13
// baseline (speedup 1.0000x reference)
#include <cuda_runtime.h>
#include <cuda_bf16.h>
#include <cuda_fp16.h>
#include <mma.h>
#include <cstdint>

using namespace nvcuda;
typedef __nv_bfloat16 bf16;

#define T_STEPS 256
#define BATCH   512
#define DIM     512
#define HID     512
#define NQV     8
#define NTOT    2048
#define MROWS   (T_STEPS*BATCH)
#define ALPHA_F 0.7f
#define ALPHB_F 0.3f
#define NBLOCKS 128

// ---------------- device-global scratch (no allocations allowed) ------------
__device__ float g_XP[(size_t)MROWS * NTOT];      // x-part preacts (interleaved cols)
__device__ float g_XQ[(size_t)MROWS * NQV];       // x-part of q_in + bq
// X fused fp16 hi|lo chunk blocks: [mtile(1024)][kchunk(16)]{hi 128x40 | lo 128x40}
__device__ __align__(256) half g_Xc[(size_t)1024 * 16 * 10240];
// Wx fp16 single chunk blocks: [ntile(16)][kchunk(16)][k(32)][npad(136)]
__device__ __align__(256) half g_Wxc[16 * 16 * 4352];
__device__ bf16  g_WhHi[512 * NTOT];              // [k][4j+g] = Wg[512+k][j] (plain)
__device__ bf16  g_WhLo[512 * NTOT];
__device__ float g_biasI[NTOT];                   // [4j+g] = b_g[j]
// h fused hi|lo chunk blocks (pre-padded A-tile images):
// [buf(2)][mt(4)][kc(16)]{hi col(32)x136row | lo col(32)x136row} bf16 = 17408B/chunk
__device__ __align__(256) bf16 g_hT[2 * 4 * 16 * 8704];
__device__ unsigned g_arr[4];
__device__ volatile unsigned g_genA[4];

__device__ __forceinline__ float ex2f(float x){ float r; asm("ex2.approx.f32 %0,%1;":"=f"(r):"f"(x)); return r; }
__device__ __forceinline__ float rcpf(float x){ float r; asm("rcp.approx.f32 %0,%1;":"=f"(r):"f"(x)); return r; }
#define LOG2E 1.4426950408889634f
__device__ __forceinline__ float sigm_f(float x) { return rcpf(1.f + ex2f(-x * LOG2E)); }
__device__ __forceinline__ float tanh_f(float x) { return 2.f * rcpf(1.f + ex2f(-2.f * x * LOG2E)) - 1.f; }

// ---- bulk async copy + mbarrier helpers (baseline sm_90 PTX, ok on compute_103) ----
__device__ __forceinline__ void bulk_cp(unsigned dst_s, const void* src, unsigned bytes, unsigned mbar_s) {
    asm volatile("cp.async.bulk.shared::cta.global.mbarrier::complete_tx::bytes [%0], [%1], %2, [%3];"
                 :: "r"(dst_s), "l"(src), "r"(bytes), "r"(mbar_s) : "memory");
}
__device__ __forceinline__ void mbar_init(unsigned mbar_s, unsigned cnt) {
    asm volatile("mbarrier.init.shared.b64 [%0], %1;" :: "r"(mbar_s), "r"(cnt) : "memory");
}
__device__ __forceinline__ void mbar_expect(unsigned mbar_s, unsigned bytes) {
    asm volatile("mbarrier.arrive.expect_tx.shared.b64 _, [%0], %1;" :: "r"(mbar_s), "r"(bytes) : "memory");
}
__device__ __forceinline__ void mbar_arrive(unsigned mbar_s) {
    asm volatile("mbarrier.arrive.shared.b64 _, [%0];" :: "r"(mbar_s) : "memory");
}
__device__ __forceinline__ void mbar_wait(unsigned mbar_s, unsigned parity) {
    asm volatile(
        "{\n\t.reg .pred P;\n"
        "LW_%=:\n\t"
        "mbarrier.try_wait.parity.acquire.cta.shared::cta.b64 P, [%0], %1, 0x989680;\n\t"
        "@P bra LD_%=;\n\t"
        "bra LW_%=;\n"
        "LD_%=:\n\t}"
        :: "r"(mbar_s), "r"(parity) : "memory");
}
#define FENCE_ASYNC() asm volatile("fence.proxy.async.shared::cta;" ::: "memory")

// ---------------- init: zero h buffer + barrier state ------------------------
__global__ void zero_state() {
    int i = blockIdx.x * blockDim.x + threadIdx.x;
    if (i < 2 * 4 * 16 * 8704) g_hT[i] = __float2bfloat16(0.f);
    if (i < 4) { g_arr[i] = 0; g_genA[i] = 0; }
}

// ---------------- split inputs into fused fp16 hi|lo chunk blocks -------------
__global__ void cvt_x(const float* __restrict__ x) {
    size_t i = (size_t)blockIdx.x * blockDim.x + threadIdx.x;
    if (i >= (size_t)MROWS * DIM) return;
    size_t m = i >> 9;
    int k = (int)(i & 511);
    int mtile = (int)(m >> 7), r = (int)(m & 127);
    int kc = k >> 5, kk = k & 31;
    size_t base = (size_t)(mtile * 16 + kc) * 10240 + (size_t)r * 40 + kk;
    float v = x[i];
    half h = __float2half_rn(v);
    g_Xc[base] = h;
    g_Xc[base + 5120] = __float2half_rn(v - __half2float(h));
}

// ---------------- build interleaved split weights + bias ----------------------
__global__ void cvt_w(const float* __restrict__ w0, const float* __restrict__ w1,
                      const float* __restrict__ w2, const float* __restrict__ w3,
                      const float* __restrict__ b0, const float* __restrict__ b1,
                      const float* __restrict__ b2, const float* __restrict__ b3) {
    int i = blockIdx.x * blockDim.x + threadIdx.x;
    if (i >= 512 * NTOT) return;
    int k = i >> 11, np = i & (NTOT - 1);
    int j = np >> 2, g = np & 3;
    const float* W = (g == 0) ? w0 : (g == 1) ? w1 : (g == 2) ? w2 : w3;
    float vx = W[(size_t)k * 512 + j];
    float vh = W[(size_t)(512 + k) * 512 + j];
    int ntile = np >> 7, n = np & 127, kc = k >> 5, kk = k & 31;
    g_Wxc[(size_t)(ntile * 16 + kc) * 4352 + (size_t)kk * 136 + n] = __float2half_rn(vx);
    bf16 hh = __float2bfloat16_rn(vh);
    g_WhHi[i] = hh;
    g_WhLo[i] = __float2bfloat16_rn(vh - __bfloat162float(hh));
    if (k == 0) {
        const float* B = (g == 0) ? b0 : (g == 1) ? b1 : (g == 2) ? b2 : b3;
        g_biasI[np] = B[j];
    }
}

// ---------------- XQ = inputs @ Wq[0:512] + bq -------------------------------
__global__ void __launch_bounds__(512) xq_kernel(
    const float* __restrict__ inputs, const float* __restrict__ Wq,
    const float* __restrict__ bq)
{
    __shared__ float sWq[NQV * 513];
    __shared__ float sBq[NQV];
    int tid = threadIdx.x;
    for (int i = tid; i < 512 * NQV; i += 512) {
        int k = i >> 3, q = i & 7;
        sWq[q * 513 + k] = Wq[(size_t)k * NQV + q];
    }
    if (tid < NQV) sBq[tid] = bq[tid];
    __syncthreads();

    int gw   = blockIdx.x * 16 + (tid >> 5);
    int lane = tid & 31;
    const float* x = inputs + (size_t)gw * DIM;
    float acc[NQV];
    #pragma unroll
    for (int q = 0; q < NQV; q++) acc[q] = 0.f;
    #pragma unroll 4
    for (int k = lane; k < DIM; k += 32) {
        float xv = x[k];
        #pragma unroll
        for (int q = 0; q < NQV; q++) acc[q] += xv * sWq[q * 513 + k];
    }
    #pragma unroll
    for (int q = 0; q < NQV; q++) {
        float v = acc[q];
        #pragma unroll
        for (int off = 16; off; off >>= 1) v += __shfl_xor_sync(0xffffffffu, v, off);
        acc[q] = v;
    }
    if (lane == 0) {
        #pragma unroll
        for (int q = 0; q < NQV; q++) g_XQ[(size_t)gw * NQV + q] = acc[q] + sBq[q];
    }
}

// ---------------- precompute GEMM: XP = (Xhi+Xlo) @ Wf16 (fp16 x2, bulk-TMA) --
#define GA_LD 40
#define GB_LD 136
#define GXS_AHI 0
#define GXS_ALO 10240
#define GXS_B   20480
#define GXS_SZ  29184
#define GXS_MB  (3 * GXS_SZ)
#define GX_TOTAL (GXS_MB + 128)
__global__ void __launch_bounds__(256, 2) gemm_x()
{
    extern __shared__ char smem[];
    const unsigned su = (unsigned)__cvta_generic_to_shared(smem);
    const int tid = threadIdx.x;
    const int ntile = blockIdx.x;
    const int mtile = blockIdx.y;
    const int n0 = ntile * 128;
    const size_t m0 = (size_t)mtile * 128;

    const int warp = tid >> 5;
    const int wr = warp & 3;
    const int wc = warp >> 2;

    if (tid == 0) {
        #pragma unroll
        for (int s = 0; s < 3; ++s) mbar_init(su + GXS_MB + s * 8, 1);
    }
    __syncthreads();
    int ph[3] = {0, 0, 0};

    wmma::fragment<wmma::accumulator, 16, 16, 16, float> acc[2][4];
    #pragma unroll
    for (int i = 0; i < 2; i++)
        #pragma unroll
        for (int j = 0; j < 4; j++) wmma::fill_fragment(acc[i][j], 0.f);

    auto issue = [&](int kc) {
        if (tid == 0) {
            int s = kc % 3;
            unsigned mb = su + GXS_MB + s * 8;
            mbar_expect(mb, GXS_SZ);
            unsigned d = su + s * GXS_SZ;
            bulk_cp(d + GXS_AHI, g_Xc  + ((size_t)mtile * 16 + kc) * 10240, 20480, mb);
            bulk_cp(d + GXS_B,   g_Wxc + ((size_t)ntile * 16 + kc) * 4352,  8704,  mb);
        }
    };

    issue(0); issue(1);
    for (int kc = 0; kc < 16; ++kc) {
        if (kc < 14) issue(kc + 2);
        int s = kc % 3;
        mbar_wait(su + GXS_MB + s * 8, ph[s]); ph[s] ^= 1;

        char* base = smem + s * GXS_SZ;
        const half* Ahi = (const half*)(base + GXS_AHI);
        const half* Alo = (const half*)(base + GXS_ALO);
        const half* B   = (const half*)(base + GXS_B);
        #pragma unroll
        for (int ks = 0; ks < 2; ++ks) {
            wmma::fragment<wmma::matrix_a, 16, 16, 16, half, wmma::row_major> ahi[2], alo[2];
            wmma::fragment<wmma::matrix_b, 16, 16, 16, half, wmma::row_major> b[4];
            #pragma unroll
            for (int i = 0; i < 2; i++) {
                wmma::load_matrix_sync(ahi[i], Ahi + (wr * 32 + i * 16) * GA_LD + ks * 16, GA_LD);
                wmma::load_matrix_sync(alo[i], Alo + (wr * 32 + i * 16) * GA_LD + ks * 16, GA_LD);
            }
            #pragma unroll
            for (int j = 0; j < 4; j++)
                wmma::load_matrix_sync(b[j], B + (ks * 16) * GB_LD + wc * 64 + j * 16, GB_LD);
            #pragma unroll
            for (int i = 0; i < 2; i++)
                #pragma unroll
                for (int j = 0; j < 4; j++) {
                    wmma::mma_sync(acc[i][j], ahi[i], b[j], acc[i][j]);
                    wmma::mma_sync(acc[i][j], alo[i], b[j], acc[i][j]);
                }
        }
        __syncthreads();
    }
    #pragma unroll
    for (int i = 0; i < 2; i++)
        #pragma unroll
        for (int j = 0; j < 4; j++) {
            size_t row0 = m0 + wr * 32 + i * 16;
            int    col0 = n0 + wc * 64 + j * 16;
            wmma::store_matrix_sync(g_XP + row0 * NTOT + col0, acc[i][j], NTOT, wmma::mem_row_major);
        }
}

// ---------------- persistent recurrent kernel (warp-specialized producer) -----
#define SW_HI   0         // 512 x 72 bf16 = 73728
#define SW_LO   73728
#define SQWF    147456    // 512 x 8 f32 = 16384 (full-precision WqH)
#define ST_A    163840    // 3 stages x 17408 (hi 32x136 bf16, lo at +8704)
#define ST_ABUF 17408
#define SBIAS   216064
#define SWQHS   216320
#define SBQH    216832
#define STH     216896
#define SMB_FULL 217024   // 3 full barriers
#define SMB_CONS 217056   // 3 consumed barriers (count=16)
#define PS_TOTAL 217088
// epilogue alias over ST_A: sP 128x68 f32 (34816B), sQ 512x8 f32 @+34816 (16384B)

#define W_LD  72
#define A_LD  136
#define SP_LD 68

__global__ void __launch_bounds__(544) qlstm_persistent(
    const float* __restrict__ Wq,  const float* __restrict__ Wqh,
    const float* __restrict__ bqh,
    const float* __restrict__ thf, const float* __restrict__ thi,
    const float* __restrict__ thu, const float* __restrict__ tho,
    float* __restrict__ out, int tails)
{
    extern __shared__ char smem[];
    const unsigned su = (unsigned)__cvta_generic_to_shared(smem);
    const int tid = threadIdx.x;
    const int bx = blockIdx.x;
    const int mt = bx >> 5, nt = bx & 31;
    const int m0 = mt * 128;
    const int nc0 = nt * 64;
    const int warp = tid >> 5;
    const int lane = tid & 31;
    const int wr = warp >> 1;            // 0..7 : 16 rows each (consumer warps)
    const int wc = warp & 1;             // 0..1 : 32 cols each

    bf16* sWhi = (bf16*)(smem + SW_HI);
    bf16* sWlo = (bf16*)(smem + SW_LO);
    for (int i = tid; i < 512 * 64; i += 544) {
        int k = i >> 6, n = i & 63;
        sWhi[k * W_LD + n] = g_WhHi[(size_t)k * NTOT + nc0 + n];
        sWlo[k * W_LD + n] = g_WhLo[(size_t)k * NTOT + nc0 + n];
    }
    float* sWqHf = (float*)(smem + SQWF);   // [k][q] f32
    for (int i = tid; i < 512 * 8; i += 544)
        sWqHf[i] = Wq[(size_t)(512 + (i >> 3)) * NQV + (i & 7)];
    float* sBias = (float*)(smem + SBIAS);
    if (tid < 64) sBias[tid] = g_biasI[nc0 + tid];
    float* sWqhS = (float*)(smem + SWQHS);
    if (tid < 128) sWqhS[tid] = Wqh[(size_t)(tid >> 4) * HID + nt * 16 + (tid & 15)];
    float* sBqh = (float*)(smem + SBQH);
    if (tid < 16) sBqh[tid] = bqh[nt * 16 + tid];
    float* sTh = (float*)(smem + STH);
    if (tid < 32) {
        int g = tid >> 3, q = tid & 7;
        sTh[tid] = (g == 0) ? thf[q] : (g == 1) ? thi[q] : (g == 2) ? thu[q] : tho[q];
    }
    if (tid == 0) {
        #pragma unroll
        for (int s = 0; s < 3; ++s) {
            mbar_init(su + SMB_FULL + s * 8, 1);
            mbar_init(su + SMB_CONS + s * 8, 16);
        }
    }
    FENCE_ASYNC();
    float c_state[4];
    #pragma unroll
    for (int i = 0; i < 4; i++) c_state[i] = 0.f;
    __syncthreads();

    for (int t = 0; t < T_STEPS; ++t) {
        const int rbuf = t & 1, wbuf = rbuf ^ 1;

        // prefetch XP/XQ for this step (independent of h) — hides DRAM latency
        float4 xv0, xv1, xv2, xv3, xqa, xqb;
        if (tid < 512) {
            const int r = tid >> 2, qd = tid & 3;
            const float4* xp4 = (const float4*)(g_XP + ((size_t)t * BATCH + m0 + r) * NTOT + nc0 + qd * 16);
            xv0 = xp4[0]; xv1 = xp4[1]; xv2 = xp4[2]; xv3 = xp4[3];
            const float4* xqp = (const float4*)(g_XQ + ((size_t)t * BATCH + m0 + r) * NQV);
            xqa = xqp[0]; xqb = xqp[1];
        }

        if (tid == 512) {
            // --- producer: inter-block barrier (h ready), then stream 16 chunks ---
            if (t > 0) {
                __threadfence();
                unsigned gen = g_genA[mt];
                if (atomicAdd(&g_arr[mt], 1u) == 31u) {
                    g_arr[mt] = 0;
                    __threadfence();
                    g_genA[mt] = gen + 1;
                } else {
                    while (g_genA[mt] == gen) { }
                    __threadfence();
                }
            }
            const char* hSrc = (const char*)g_hT + (size_t)((rbuf * 4 + mt) * 16) * 17408;
            #pragma unroll
            for (int kc = 0; kc < 16; ++kc) {
                int s = kc % 3;
                int nu = t * ((s == 0) ? 6 : 5) + kc / 3;
                if (nu > 0) mbar_wait(su + SMB_CONS + s * 8, (nu - 1) & 1);
                unsigned mb = su + SMB_FULL + s * 8;
                mbar_expect(mb, 17408);
                bulk_cp(su + ST_A + s * ST_ABUF, hSrc + (size_t)kc * 17408, 17408, mb);
            }
        }

        wmma::fragment<wmma::accumulator, 16, 16, 16, float> acch[2], accx[2];
        float qacc[NQV];
        if (tid < 512) {
            #pragma unroll
            for (int j = 0; j < 2; j++) { wmma::fill_fragment(acch[j], 0.f); wmma::fill_fragment(accx[j], 0.f); }
            #pragma unroll
            for (int q = 0; q < NQV; q++) qacc[q] = 0.f;

            const int qr = tid >> 2;     // q-row (4 threads per row)
            const int qp = tid & 3;      // part

            #pragma unroll
            for (int kc = 0; kc < 16; ++kc) {
                int s = kc % 3;
                int nu = t * ((s == 0) ? 6 : 5) + kc / 3;
                mbar_wait(su + SMB_FULL + s * 8, nu & 1);

                const bf16* Ahi = (const bf16*)(smem + ST_A + s * ST_ABUF);
                const bf16* Alo = (const bf16*)(smem + ST_A + s * ST_ABUF + 8704);
                const int kb = kc * 32;
                #pragma unroll
                for (int ks = 0; ks < 2; ++ks) {
                    wmma::fragment<wmma::matrix_a, 16, 16, 16, bf16, wmma::col_major> ahi, alo;
                    wmma::load_matrix_sync(ahi, Ahi + (ks * 16) * A_LD + wr * 16, A_LD);
                    wmma::load_matrix_sync(alo, Alo + (ks * 16) * A_LD + wr * 16, A_LD);
                    #pragma unroll
                    for (int j = 0; j < 2; j++) {
                        wmma::fragment<wmma::matrix_b, 16, 16, 16, bf16, wmma::row_major> bhi, blo;
                        wmma::load_matrix_sync(bhi, sWhi + (kb + ks * 16) * W_LD + wc * 32 + j * 16, W_LD);
                        wmma::load_matrix_sync(blo, sWlo + (kb + ks * 16) * W_LD + wc * 32 + j * 16, W_LD);
                        wmma::mma_sync(acch[j], ahi, bhi, acch[j]);
                        wmma::mma_sync(accx[j], ahi, blo, accx[j]);
                        wmma::mma_sync(accx[j], alo, bhi, accx[j]);
                    }
                }
                // scalar q partial on the fma pipe (tensor stays saturated):
                // kk = qp + 4*i  (rotated to avoid smem bank conflicts)
                #pragma unroll
                for (int i = 0; i < 8; ++i) {
                    int kk = qp + 4 * i;
                    float hv = __bfloat162float(Ahi[kk * A_LD + qr])
                             + __bfloat162float(Alo[kk * A_LD + qr]);
                    const float* wq = sWqHf + (kb + kk) * 8;
                    #pragma unroll
                    for (int q = 0; q < NQV; q++) qacc[q] += hv * wq[q];
                }
                if (lane == 0) mbar_arrive(su + SMB_CONS + s * 8);
            }
        }
        __syncthreads();   // all MMAs + q reads done; stage smem reusable as sP/sQ

        float* sP = (float*)(smem + ST_A);
        float* sQ = (float*)(smem + ST_A + 34816);
        if (tid < 512) {
            #pragma unroll
            for (int j = 0; j < 2; j++) {
                #pragma unroll
                for (int e = 0; e < acch[j].num_elements; ++e) acch[j].x[e] += accx[j].x[e];
                wmma::store_matrix_sync(sP + (wr * 16) * SP_LD + wc * 32 + j * 16, acch[j], SP_LD, wmma::mem_row_major);
            }
            #pragma unroll
            for (int q = 0; q < NQV; q++) sQ[tid * 8 + q] = qacc[q];
        }
        __syncthreads();

        if (tid < 512) {
            // phase1: thread = (row, gate): qin + cumprod(cos)
            const int r = tid >> 2;
            const int gq = tid & 3;
            float z[NQV];
            {
                float xqv[NQV] = {xqa.x, xqa.y, xqa.z, xqa.w, xqb.x, xqb.y, xqb.z, xqb.w};
                float run = 1.f;
                #pragma unroll
                for (int q = 0; q < NQV; ++q) {
                    float qin = sQ[(r * 4 + 0) * 8 + q] + sQ[(r * 4 + 1) * 8 + q]
                              + sQ[(r * 4 + 2) * 8 + q] + sQ[(r * 4 + 3) * 8 + q] + xqv[q];
                    run *= __cosf(qin + sTh[gq * 8 + q]);
                    z[q] = run;
                }
            }
            float zz[4][NQV];
            {
                const int lb = lane & ~3;
                #pragma unroll
                for (int g = 0; g < 4; ++g)
                    #pragma unroll
                    for (int q = 0; q < NQV; ++q)
                        zz[g][q] = __shfl_sync(0xffffffffu, z[q], lb + g);
            }

            // phase2: thread = (row, col-quad): combine + LSTM update + h write
            const int qd = gq;
            const int rowg = m0 + r;
            const float* sPr = sP + r * SP_LD + qd * 16;
            const float* sBq_ = sBias + qd * 16;
            const size_t ob = ((size_t)t * BATCH + rowg) * HID;
            float4 xvv[4] = {xv0, xv1, xv2, xv3};
            float4 h4;
            float* h4p = (float*)&h4;
            #pragma unroll
            for (int jj = 0; jj < 4; ++jj) {
                int jl = qd * 4 + jj;
                int jg = nt * 16 + jl;
                float4 xvq = xvv[jj];
                float p0 = sPr[jj * 4 + 0] + xvq.x + sBq_[jj * 4 + 0];
                float p1 = sPr[jj * 4 + 1] + xvq.y + sBq_[jj * 4 + 1];
                float p2 = sPr[jj * 4 + 2] + xvq.z + sBq_[jj * 4 + 2];
                float p3 = sPr[jj * 4 + 3] + xvq.w + sBq_[jj * 4 + 3];
                float a0 = sBqh[jl], a1 = a0, a2 = a0, a3 = a0;
                #pragma unroll
                for (int q = 0; q < NQV; q++) {
                    float w = sWqhS[q * 16 + jl];
                    a0 += zz[0][q] * w;
                    a1 += zz[1][q] * w;
                    a2 += zz[2][q] * w;
                    a3 += zz[3][q] * w;
                }
                float f  = ALPHA_F * sigm_f(p0)  + ALPHB_F * sigm_f(a0);
                float ii = ALPHA_F * sigm_f(p1)  + ALPHB_F * sigm_f(a1);
                float gg = ALPHA_F * tanh_f(p2)  + ALPHB_F * tanh_f(a2);
                float oo = ALPHA_F * sigm_f(p3)  + ALPHB_F * sigm_f(a3);
                float cn = f * c_state[jj] + ii * gg;
                float hn = oo * tanh_f(cn);
                c_state[jj] = cn;
                h4p[jj] = hn;
                bf16 hh = __float2bfloat16_rn(hn);
                bf16 hl = __float2bfloat16_rn(hn - __bfloat162float(hh));
                size_t hbase = (size_t)((wbuf * 4 + mt) * 16 + (jg >> 5)) * 8704
                             + (size_t)(jg & 31) * 136 + r;
                g_hT[hbase] = hh;
                g_hT[hbase + 4352] = hl;
                if (t == T_STEPS - 1 && tails) {
                    size_t outT = (size_t)T_STEPS * BATCH * HID;
                    out[outT + (size_t)rowg * HID + jg] = hn;
                    out[outT + (size_t)BATCH * HID + (size_t)rowg * HID + jg] = cn;
                }
            }
            *(float4*)(out + ob + nt * 16 + qd * 4) = h4;
        }

        FENCE_ASYNC();      // order generic sP/sQ writes before next step's TMA
        __syncthreads();    // producer may now re-enter; h writes block-visible
    }
}

// ---------------- launch ------------------------------------------------------
extern "C" void kernel_launch(void* const* d_in, const int* in_sizes, int n_in,
                              void* d_out, int out_size)
{
    const float* inputs = (const float*)d_in[0];
    const float* Wf = (const float*)d_in[1];
    const float* bf_ = (const float*)d_in[2];
    const float* Wi = (const float*)d_in[3];
    const float* bi = (const float*)d_in[4];
    const float* Wu = (const float*)d_in[5];
    const float* bu = (const float*)d_in[6];
    const float* Wo = (const float*)d_in[7];
    const float* bo = (const float*)d_in[8];
    const float* Wq = (const float*)d_in[9];
    const float* bq = (const float*)d_in[10];
    const float* Wqh = (const float*)d_in[11];
    const float* bqh = (const float*)d_in[12];
    const float* th_f = (const float*)d_in[13];
    const float* th_i = (const float*)d_in[14];
    const float* th_u = (const float*)d_in[15];
    const float* th_o = (const float*)d_in[16];
    float* out = (float*)d_out;

    cudaFuncSetAttribute(gemm_x, cudaFuncAttributeMaxDynamicSharedMemorySize, GX_TOTAL);
    cudaFuncSetAttribute(qlstm_persistent, cudaFuncAttributeMaxDynamicSharedMemorySize, PS_TOTAL);

    const size_t outT = (size_t)T_STEPS * BATCH * HID;
    int tails = ((size_t)out_size >= outT + 2 * (size_t)BATCH * HID) ? 1 : 0;

    zero_state<<<(2 * 4 * 16 * 8704 + 255) / 256, 256>>>();
    cvt_x<<<(int)(((size_t)MROWS * DIM + 255) / 256), 256>>>(inputs);
    cvt_w<<<(512 * NTOT + 255) / 256, 256>>>(Wf, Wi, Wu, Wo, bf_, bi, bu, bo);
    xq_kernel<<<MROWS / 16, 512>>>(inputs, Wq, bq);
    gemm_x<<<dim3(16, MROWS / 128), 256, GX_TOTAL>>>();
    qlstm_persistent<<<NBLOCKS, 544, PS_TOTAL>>>(
        Wq, Wqh, bqh, th_f, th_i, th_u, th_o, out, tails);
}

// round 16
// speedup vs baseline: 1.1810x; 1.1810x over previous
#include <cuda_runtime.h>
#include <cuda_bf16.h>
#include <cuda_fp16.h>
#include <mma.h>
#include <cstdint>

using namespace nvcuda;
typedef __nv_bfloat16 bf16;

#define T_STEPS 256
#define BATCH   512
#define DIM     512
#define HID     512
#define NQV     8
#define NTOT    2048
#define MROWS   (T_STEPS*BATCH)
#define ALPHA_F 0.7f
#define ALPHB_F 0.3f
#define NBLOCKS 128

// ---------------- device-global scratch (no allocations allowed) ------------
__device__ float g_XP[(size_t)MROWS * NTOT];      // x-part preacts (interleaved cols)
__device__ float g_XQ[(size_t)MROWS * NQV];       // x-part of q_in + bq
// X fused fp16 hi|lo chunk blocks: [mtile(1024)][kchunk(16)]{hi 128x40 | lo 128x40}
__device__ __align__(256) half g_Xc[(size_t)1024 * 16 * 10240];
// Wx fp16 single chunk blocks: [ntile(16)][kchunk(16)][k(32)][npad(136)]
__device__ __align__(256) half g_Wxc[16 * 16 * 4352];
__device__ bf16  g_WhHi[512 * NTOT];              // [k][4j+g] = Wg[512+k][j] (plain)
__device__ bf16  g_WhLo[512 * NTOT];
__device__ float g_biasI[NTOT];                   // [4j+g] = b_g[j]
// h fused hi|lo chunk blocks (pre-padded A-tile images):
// [buf(2)][mt(4)][kc(16)]{hi col(32)x136row | lo col(32)x136row} bf16 = 17408B/chunk
__device__ __align__(256) bf16 g_hT[2 * 4 * 16 * 8704];
__device__ unsigned g_arr[4];
__device__ volatile unsigned g_genA[4];

__device__ __forceinline__ float ex2f(float x){ float r; asm("ex2.approx.f32 %0,%1;":"=f"(r):"f"(x)); return r; }
__device__ __forceinline__ float rcpf(float x){ float r; asm("rcp.approx.f32 %0,%1;":"=f"(r):"f"(x)); return r; }
#define LOG2E 1.4426950408889634f
__device__ __forceinline__ float sigm_f(float x) { return rcpf(1.f + ex2f(-x * LOG2E)); }
__device__ __forceinline__ float tanh_f(float x) { return 2.f * rcpf(1.f + ex2f(-2.f * x * LOG2E)) - 1.f; }

// ---- bulk async copy + mbarrier helpers (baseline sm_90 PTX, ok on compute_103) ----
__device__ __forceinline__ void bulk_cp(unsigned dst_s, const void* src, unsigned bytes, unsigned mbar_s) {
    asm volatile("cp.async.bulk.shared::cta.global.mbarrier::complete_tx::bytes [%0], [%1], %2, [%3];"
                 :: "r"(dst_s), "l"(src), "r"(bytes), "r"(mbar_s) : "memory");
}
__device__ __forceinline__ void mbar_init(unsigned mbar_s, unsigned cnt) {
    asm volatile("mbarrier.init.shared.b64 [%0], %1;" :: "r"(mbar_s), "r"(cnt) : "memory");
}
__device__ __forceinline__ void mbar_expect(unsigned mbar_s, unsigned bytes) {
    asm volatile("mbarrier.arrive.expect_tx.shared.b64 _, [%0], %1;" :: "r"(mbar_s), "r"(bytes) : "memory");
}
__device__ __forceinline__ void mbar_arrive(unsigned mbar_s) {
    asm volatile("mbarrier.arrive.shared.b64 _, [%0];" :: "r"(mbar_s) : "memory");
}
__device__ __forceinline__ void mbar_wait(unsigned mbar_s, unsigned parity) {
    asm volatile(
        "{\n\t.reg .pred P;\n"
        "LW_%=:\n\t"
        "mbarrier.try_wait.parity.acquire.cta.shared::cta.b64 P, [%0], %1, 0x989680;\n\t"
        "@P bra LD_%=;\n\t"
        "bra LW_%=;\n"
        "LD_%=:\n\t}"
        :: "r"(mbar_s), "r"(parity) : "memory");
}
#define FENCE_ASYNC() asm volatile("fence.proxy.async.shared::cta;" ::: "memory")

// ---------------- init: zero h buffer + barrier state ------------------------
__global__ void zero_state() {
    int i = blockIdx.x * blockDim.x + threadIdx.x;
    if (i < 2 * 4 * 16 * 8704) g_hT[i] = __float2bfloat16(0.f);
    if (i < 4) { g_arr[i] = 0; g_genA[i] = 0; }
}

// ---------------- split inputs into fused fp16 hi|lo chunk blocks -------------
__global__ void cvt_x(const float* __restrict__ x) {
    size_t i = (size_t)blockIdx.x * blockDim.x + threadIdx.x;
    if (i >= (size_t)MROWS * DIM) return;
    size_t m = i >> 9;
    int k = (int)(i & 511);
    int mtile = (int)(m >> 7), r = (int)(m & 127);
    int kc = k >> 5, kk = k & 31;
    size_t base = (size_t)(mtile * 16 + kc) * 10240 + (size_t)r * 40 + kk;
    float v = x[i];
    half h = __float2half_rn(v);
    g_Xc[base] = h;
    g_Xc[base + 5120] = __float2half_rn(v - __half2float(h));
}

// ---------------- build interleaved split weights + bias ----------------------
__global__ void cvt_w(const float* __restrict__ w0, const float* __restrict__ w1,
                      const float* __restrict__ w2, const float* __restrict__ w3,
                      const float* __restrict__ b0, const float* __restrict__ b1,
                      const float* __restrict__ b2, const float* __restrict__ b3) {
    int i = blockIdx.x * blockDim.x + threadIdx.x;
    if (i >= 512 * NTOT) return;
    int k = i >> 11, np = i & (NTOT - 1);
    int j = np >> 2, g = np & 3;
    const float* W = (g == 0) ? w0 : (g == 1) ? w1 : (g == 2) ? w2 : w3;
    float vx = W[(size_t)k * 512 + j];
    float vh = W[(size_t)(512 + k) * 512 + j];
    int ntile = np >> 7, n = np & 127, kc = k >> 5, kk = k & 31;
    g_Wxc[(size_t)(ntile * 16 + kc) * 4352 + (size_t)kk * 136 + n] = __float2half_rn(vx);
    bf16 hh = __float2bfloat16_rn(vh);
    g_WhHi[i] = hh;
    g_WhLo[i] = __float2bfloat16_rn(vh - __bfloat162float(hh));
    if (k == 0) {
        const float* B = (g == 0) ? b0 : (g == 1) ? b1 : (g == 2) ? b2 : b3;
        g_biasI[np] = B[j];
    }
}

// ---------------- XQ = inputs @ Wq[0:512] + bq -------------------------------
__global__ void __launch_bounds__(512) xq_kernel(
    const float* __restrict__ inputs, const float* __restrict__ Wq,
    const float* __restrict__ bq)
{
    __shared__ float sWq[NQV * 513];
    __shared__ float sBq[NQV];
    int tid = threadIdx.x;
    for (int i = tid; i < 512 * NQV; i += 512) {
        int k = i >> 3, q = i & 7;
        sWq[q * 513 + k] = Wq[(size_t)k * NQV + q];
    }
    if (tid < NQV) sBq[tid] = bq[tid];
    __syncthreads();

    int gw   = blockIdx.x * 16 + (tid >> 5);
    int lane = tid & 31;
    const float* x = inputs + (size_t)gw * DIM;
    float acc[NQV];
    #pragma unroll
    for (int q = 0; q < NQV; q++) acc[q] = 0.f;
    #pragma unroll 4
    for (int k = lane; k < DIM; k += 32) {
        float xv = x[k];
        #pragma unroll
        for (int q = 0; q < NQV; q++) acc[q] += xv * sWq[q * 513 + k];
    }
    #pragma unroll
    for (int q = 0; q < NQV; q++) {
        float v = acc[q];
        #pragma unroll
        for (int off = 16; off; off >>= 1) v += __shfl_xor_sync(0xffffffffu, v, off);
        acc[q] = v;
    }
    if (lane == 0) {
        #pragma unroll
        for (int q = 0; q < NQV; q++) g_XQ[(size_t)gw * NQV + q] = acc[q] + sBq[q];
    }
}

// ---------------- precompute GEMM: XP = (Xhi+Xlo) @ Wf16 (fp16 x2, bulk-TMA) --
#define GA_LD 40
#define GB_LD 136
#define GXS_AHI 0
#define GXS_ALO 10240
#define GXS_B   20480
#define GXS_SZ  29184
#define GXS_MB  (3 * GXS_SZ)
#define GX_TOTAL (GXS_MB + 128)
__global__ void __launch_bounds__(256, 2) gemm_x()
{
    extern __shared__ char smem[];
    const unsigned su = (unsigned)__cvta_generic_to_shared(smem);
    const int tid = threadIdx.x;
    const int ntile = blockIdx.x;
    const int mtile = blockIdx.y;
    const int n0 = ntile * 128;
    const size_t m0 = (size_t)mtile * 128;

    const int warp = tid >> 5;
    const int wr = warp & 3;
    const int wc = warp >> 2;

    if (tid == 0) {
        #pragma unroll
        for (int s = 0; s < 3; ++s) mbar_init(su + GXS_MB + s * 8, 1);
    }
    __syncthreads();
    int ph[3] = {0, 0, 0};

    wmma::fragment<wmma::accumulator, 16, 16, 16, float> acc[2][4];
    #pragma unroll
    for (int i = 0; i < 2; i++)
        #pragma unroll
        for (int j = 0; j < 4; j++) wmma::fill_fragment(acc[i][j], 0.f);

    auto issue = [&](int kc) {
        if (tid == 0) {
            int s = kc % 3;
            unsigned mb = su + GXS_MB + s * 8;
            mbar_expect(mb, GXS_SZ);
            unsigned d = su + s * GXS_SZ;
            bulk_cp(d + GXS_AHI, g_Xc  + ((size_t)mtile * 16 + kc) * 10240, 20480, mb);
            bulk_cp(d + GXS_B,   g_Wxc + ((size_t)ntile * 16 + kc) * 4352,  8704,  mb);
        }
    };

    issue(0); issue(1);
    for (int kc = 0; kc < 16; ++kc) {
        if (kc < 14) issue(kc + 2);
        int s = kc % 3;
        mbar_wait(su + GXS_MB + s * 8, ph[s]); ph[s] ^= 1;

        char* base = smem + s * GXS_SZ;
        const half* Ahi = (const half*)(base + GXS_AHI);
        const half* Alo = (const half*)(base + GXS_ALO);
        const half* B   = (const half*)(base + GXS_B);
        #pragma unroll
        for (int ks = 0; ks < 2; ++ks) {
            wmma::fragment<wmma::matrix_a, 16, 16, 16, half, wmma::row_major> ahi[2], alo[2];
            wmma::fragment<wmma::matrix_b, 16, 16, 16, half, wmma::row_major> b[4];
            #pragma unroll
            for (int i = 0; i < 2; i++) {
                wmma::load_matrix_sync(ahi[i], Ahi + (wr * 32 + i * 16) * GA_LD + ks * 16, GA_LD);
                wmma::load_matrix_sync(alo[i], Alo + (wr * 32 + i * 16) * GA_LD + ks * 16, GA_LD);
            }
            #pragma unroll
            for (int j = 0; j < 4; j++)
                wmma::load_matrix_sync(b[j], B + (ks * 16) * GB_LD + wc * 64 + j * 16, GB_LD);
            #pragma unroll
            for (int i = 0; i < 2; i++)
                #pragma unroll
                for (int j = 0; j < 4; j++) {
                    wmma::mma_sync(acc[i][j], ahi[i], b[j], acc[i][j]);
                    wmma::mma_sync(acc[i][j], alo[i], b[j], acc[i][j]);
                }
        }
        __syncthreads();
    }
    #pragma unroll
    for (int i = 0; i < 2; i++)
        #pragma unroll
        for (int j = 0; j < 4; j++) {
            size_t row0 = m0 + wr * 32 + i * 16;
            int    col0 = n0 + wc * 64 + j * 16;
            wmma::store_matrix_sync(g_XP + row0 * NTOT + col0, acc[i][j], NTOT, wmma::mem_row_major);
        }
}

// ---------------- persistent recurrent kernel (warp-specialized producer) -----
// R12 structure: q-path via packed hi|lo MMA on wc==0 warps.
#define SW_HI   0         // 512 x 72 bf16 = 73728
#define SW_LO   73728
#define SQW     147456    // 512 x 24 bf16 = 24576 (cols 0-7 WqH hi, 8-15 WqH lo)
#define ST_A    172032    // 3 stages x 17408 (hi 32x136 bf16, lo at +8704)
#define ST_ABUF 17408
#define SBIAS   224256
#define SWQHS   224512
#define SBQH    225024
#define STH     225088
#define SMB_FULL 225216   // 3 full barriers
#define SMB_CONS 225240   // 3 consumed barriers (count=16)
#define PS_TOTAL 225280
// epilogue alias over ST_A: sP 128x68 f32 (34816B), sQm @+34816 (8192B)

#define W_LD  72
#define QW_LD 24
#define A_LD  136
#define SP_LD 68

__global__ void __launch_bounds__(544) qlstm_persistent(
    const float* __restrict__ Wq,  const float* __restrict__ Wqh,
    const float* __restrict__ bqh,
    const float* __restrict__ thf, const float* __restrict__ thi,
    const float* __restrict__ thu, const float* __restrict__ tho,
    float* __restrict__ out, int tails)
{
    extern __shared__ char smem[];
    const unsigned su = (unsigned)__cvta_generic_to_shared(smem);
    const int tid = threadIdx.x;
    const int bx = blockIdx.x;
    const int mt = bx >> 5, nt = bx & 31;
    const int m0 = mt * 128;
    const int nc0 = nt * 64;
    const int warp = tid >> 5;
    const int lane = tid & 31;
    const int wr = warp >> 1;            // 0..7 : 16 rows each (consumer warps)
    const int wc = warp & 1;             // 0..1 : 32 cols each

    bf16* sWhi = (bf16*)(smem + SW_HI);
    bf16* sWlo = (bf16*)(smem + SW_LO);
    for (int i = tid; i < 512 * 64; i += 544) {
        int k = i >> 6, n = i & 63;
        sWhi[k * W_LD + n] = g_WhHi[(size_t)k * NTOT + nc0 + n];
        sWlo[k * W_LD + n] = g_WhLo[(size_t)k * NTOT + nc0 + n];
    }
    bf16* sQW = (bf16*)(smem + SQW);
    for (int i = tid; i < 512 * 16; i += 544) {
        int k = i >> 4, c = i & 15;
        float v = Wq[(size_t)(512 + k) * NQV + (c & 7)];
        bf16 h = __float2bfloat16_rn(v);
        sQW[k * QW_LD + c] = (c < 8) ? h : __float2bfloat16_rn(v - __bfloat162float(h));
    }
    float* sBias = (float*)(smem + SBIAS);
    if (tid < 64) sBias[tid] = g_biasI[nc0 + tid];
    float* sWqhS = (float*)(smem + SWQHS);
    if (tid < 128) sWqhS[tid] = Wqh[(size_t)(tid >> 4) * HID + nt * 16 + (tid & 15)];
    float* sBqh = (float*)(smem + SBQH);
    if (tid < 16) sBqh[tid] = bqh[nt * 16 + tid];
    float* sTh = (float*)(smem + STH);
    if (tid < 32) {
        int g = tid >> 3, q = tid & 7;
        sTh[tid] = (g == 0) ? thf[q] : (g == 1) ? thi[q] : (g == 2) ? thu[q] : tho[q];
    }
    if (tid == 0) {
        #pragma unroll
        for (int s = 0; s < 3; ++s) {
            mbar_init(su + SMB_FULL + s * 8, 1);
            mbar_init(su + SMB_CONS + s * 8, 16);
        }
    }
    FENCE_ASYNC();
    float c_state[4];
    #pragma unroll
    for (int i = 0; i < 4; i++) c_state[i] = 0.f;
    __syncthreads();

    for (int t = 0; t < T_STEPS; ++t) {
        const int rbuf = t & 1, wbuf = rbuf ^ 1;

        // prefetch XP/XQ for this step (independent of h) — hides DRAM latency
        float4 xv0, xv1, xv2, xv3, xqa, xqb;
        if (tid < 512) {
            const int r = tid >> 2, qd = tid & 3;
            const float4* xp4 = (const float4*)(g_XP + ((size_t)t * BATCH + m0 + r) * NTOT + nc0 + qd * 16);
            xv0 = xp4[0]; xv1 = xp4[1]; xv2 = xp4[2]; xv3 = xp4[3];
            const float4* xqp = (const float4*)(g_XQ + ((size_t)t * BATCH + m0 + r) * NQV);
            xqa = xqp[0]; xqb = xqp[1];
        }

        if (tid == 512) {
            // --- producer: inter-block barrier (h ready), then stream 16 chunks ---
            if (t > 0) {
                __threadfence();
                unsigned gen = g_genA[mt];
                if (atomicAdd(&g_arr[mt], 1u) == 31u) {
                    g_arr[mt] = 0;
                    __threadfence();
                    g_genA[mt] = gen + 1;
                } else {
                    while (g_genA[mt] == gen) { }
                    __threadfence();
                }
            }
            const char* hSrc = (const char*)g_hT + (size_t)((rbuf * 4 + mt) * 16) * 17408;
            #pragma unroll
            for (int kc = 0; kc < 16; ++kc) {
                int s = kc % 3;
                int nu = t * ((s == 0) ? 6 : 5) + kc / 3;
                if (nu > 0) mbar_wait(su + SMB_CONS + s * 8, (nu - 1) & 1);
                unsigned mb = su + SMB_FULL + s * 8;
                mbar_expect(mb, 17408);
                bulk_cp(su + ST_A + s * ST_ABUF, hSrc + (size_t)kc * 17408, 17408, mb);
            }
        }

        wmma::fragment<wmma::accumulator, 16, 16, 16, float> acch[2], accx[2], accq;
        if (tid < 512) {
            #pragma unroll
            for (int j = 0; j < 2; j++) { wmma::fill_fragment(acch[j], 0.f); wmma::fill_fragment(accx[j], 0.f); }
            wmma::fill_fragment(accq, 0.f);

            #pragma unroll
            for (int kc = 0; kc < 16; ++kc) {
                int s = kc % 3;
                int nu = t * ((s == 0) ? 6 : 5) + kc / 3;
                mbar_wait(su + SMB_FULL + s * 8, nu & 1);

                const bf16* Ahi = (const bf16*)(smem + ST_A + s * ST_ABUF);
                const bf16* Alo = (const bf16*)(smem + ST_A + s * ST_ABUF + 8704);
                const int kb = kc * 32;
                #pragma unroll
                for (int ks = 0; ks < 2; ++ks) {
                    wmma::fragment<wmma::matrix_a, 16, 16, 16, bf16, wmma::col_major> ahi, alo;
                    wmma::load_matrix_sync(ahi, Ahi + (ks * 16) * A_LD + wr * 16, A_LD);
                    wmma::load_matrix_sync(alo, Alo + (ks * 16) * A_LD + wr * 16, A_LD);
                    #pragma unroll
                    for (int j = 0; j < 2; j++) {
                        wmma::fragment<wmma::matrix_b, 16, 16, 16, bf16, wmma::row_major> bhi, blo;
                        wmma::load_matrix_sync(bhi, sWhi + (kb + ks * 16) * W_LD + wc * 32 + j * 16, W_LD);
                        wmma::load_matrix_sync(blo, sWlo + (kb + ks * 16) * W_LD + wc * 32 + j * 16, W_LD);
                        wmma::mma_sync(acch[j], ahi, bhi, acch[j]);
                        wmma::mma_sync(accx[j], ahi, blo, accx[j]);
                        wmma::mma_sync(accx[j], alo, bhi, accx[j]);
                    }
                    if (wc == 0) {
                        wmma::fragment<wmma::matrix_b, 16, 16, 16, bf16, wmma::row_major> bq;
                        wmma::load_matrix_sync(bq, sQW + (kb + ks * 16) * QW_LD, QW_LD);
                        wmma::mma_sync(accq, ahi, bq, accq);
                        wmma::mma_sync(accq, alo, bq, accq);
                    }
                }
                if (lane == 0) mbar_arrive(su + SMB_CONS + s * 8);
            }
        }
        __syncthreads();   // all MMAs done; stage smem reusable as sP/sQm

        float* sP  = (float*)(smem + ST_A);
        float* sQm = (float*)(smem + ST_A + 34816);
        if (tid < 512) {
            #pragma unroll
            for (int j = 0; j < 2; j++) {
                #pragma unroll
                for (int e = 0; e < acch[j].num_elements; ++e) acch[j].x[e] += accx[j].x[e];
                wmma::store_matrix_sync(sP + (wr * 16) * SP_LD + wc * 32 + j * 16, acch[j], SP_LD, wmma::mem_row_major);
            }
            if (wc == 0)
                wmma::store_matrix_sync(sQm + (wr * 16) * 16, accq, 16, wmma::mem_row_major);
        }
        __syncthreads();

        if (tid < 512) {
            // phase1: thread = (row, gate): qin + cumprod(cos)
            const int r = tid >> 2;
            const int gq = tid & 3;
            float z[NQV];
            {
                float xqv[NQV] = {xqa.x, xqa.y, xqa.z, xqa.w, xqb.x, xqb.y, xqb.z, xqb.w};
                float run = 1.f;
                #pragma unroll
                for (int q = 0; q < NQV; ++q) {
                    float qin = sQm[r * 16 + q] + sQm[r * 16 + 8 + q] + xqv[q];
                    run *= __cosf(qin + sTh[gq * 8 + q]);
                    z[q] = run;
                }
            }
            float zz[4][NQV];
            {
                const int lb = lane & ~3;
                #pragma unroll
                for (int g = 0; g < 4; ++g)
                    #pragma unroll
                    for (int q = 0; q < NQV; ++q)
                        zz[g][q] = __shfl_sync(0xffffffffu, z[q], lb + g);
            }

            // phase2: thread = (row, col-quad): combine + LSTM update + h write
            const int qd = gq;
            const int rowg = m0 + r;
            const float* sPr = sP + r * SP_LD + qd * 16;
            const float* sBq_ = sBias + qd * 16;
            const size_t ob = ((size_t)t * BATCH + rowg) * HID;
            float4 xvv[4] = {xv0, xv1, xv2, xv3};
            float4 h4;
            float* h4p = (float*)&h4;
            #pragma unroll
            for (int jj = 0; jj < 4; ++jj) {
                int jl = qd * 4 + jj;
                int jg = nt * 16 + jl;
                float4 xvq = xvv[jj];
                float p0 = sPr[jj * 4 + 0] + xvq.x + sBq_[jj * 4 + 0];
                float p1 = sPr[jj * 4 + 1] + xvq.y + sBq_[jj * 4 + 1];
                float p2 = sPr[jj * 4 + 2] + xvq.z + sBq_[jj * 4 + 2];
                float p3 = sPr[jj * 4 + 3] + xvq.w + sBq_[jj * 4 + 3];
                float a0 = sBqh[jl], a1 = a0, a2 = a0, a3 = a0;
                #pragma unroll
                for (int q = 0; q < NQV; q++) {
                    float w = sWqhS[q * 16 + jl];
                    a0 += zz[0][q] * w;
                    a1 += zz[1][q] * w;
                    a2 += zz[2][q] * w;
                    a3 += zz[3][q] * w;
                }
                float f  = ALPHA_F * sigm_f(p0)  + ALPHB_F * sigm_f(a0);
                float ii = ALPHA_F * sigm_f(p1)  + ALPHB_F * sigm_f(a1);
                float gg = ALPHA_F * tanh_f(p2)  + ALPHB_F * tanh_f(a2);
                float oo = ALPHA_F * sigm_f(p3)  + ALPHB_F * sigm_f(a3);
                float cn = f * c_state[jj] + ii * gg;
                float hn = oo * tanh_f(cn);
                c_state[jj] = cn;
                h4p[jj] = hn;
                bf16 hh = __float2bfloat16_rn(hn);
                bf16 hl = __float2bfloat16_rn(hn - __bfloat162float(hh));
                size_t hbase = (size_t)((wbuf * 4 + mt) * 16 + (jg >> 5)) * 8704
                             + (size_t)(jg & 31) * 136 + r;
                g_hT[hbase] = hh;
                g_hT[hbase + 4352] = hl;
                if (t == T_STEPS - 1 && tails) {
                    size_t outT = (size_t)T_STEPS * BATCH * HID;
                    out[outT + (size_t)rowg * HID + jg] = hn;
                    out[outT + (size_t)BATCH * HID + (size_t)rowg * HID + jg] = cn;
                }
            }
            *(float4*)(out + ob + nt * 16 + qd * 4) = h4;
        }

        FENCE_ASYNC();      // order generic sP/sQm writes before next step's TMA
        __syncthreads();    // producer may now re-enter; h writes block-visible
    }
}

// ---------------- launch ------------------------------------------------------
extern "C" void kernel_launch(void* const* d_in, const int* in_sizes, int n_in,
                              void* d_out, int out_size)
{
    const float* inputs = (const float*)d_in[0];
    const float* Wf = (const float*)d_in[1];
    const float* bf_ = (const float*)d_in[2];
    const float* Wi = (const float*)d_in[3];
    const float* bi = (const float*)d_in[4];
    const float* Wu = (const float*)d_in[5];
    const float* bu = (const float*)d_in[6];
    const float* Wo = (const float*)d_in[7];
    const float* bo = (const float*)d_in[8];
    const float* Wq = (const float*)d_in[9];
    const float* bq = (const float*)d_in[10];
    const float* Wqh = (const float*)d_in[11];
    const float* bqh = (const float*)d_in[12];
    const float* th_f = (const float*)d_in[13];
    const float* th_i = (const float*)d_in[14];
    const float* th_u = (const float*)d_in[15];
    const float* th_o = (const float*)d_in[16];
    float* out = (float*)d_out;

    cudaFuncSetAttribute(gemm_x, cudaFuncAttributeMaxDynamicSharedMemorySize, GX_TOTAL);
    cudaFuncSetAttribute(qlstm_persistent, cudaFuncAttributeMaxDynamicSharedMemorySize, PS_TOTAL);

    const size_t outT = (size_t)T_STEPS * BATCH * HID;
    int tails = ((size_t)out_size >= outT + 2 * (size_t)BATCH * HID) ? 1 : 0;

    zero_state<<<(2 * 4 * 16 * 8704 + 255) / 256, 256>>>();
    cvt_x<<<(int)(((size_t)MROWS * DIM + 255) / 256), 256>>>(inputs);
    cvt_w<<<(512 * NTOT + 255) / 256, 256>>>(Wf, Wi, Wu, Wo, bf_, bi, bu, bo);
    xq_kernel<<<MROWS / 16, 512>>>(inputs, Wq, bq);
    gemm_x<<<dim3(16, MROWS / 128), 256, GX_TOTAL>>>();
    qlstm_persistent<<<NBLOCKS, 544, PS_TOTAL>>>(
        Wq, Wqh, bqh, th_f, th_i, th_u, th_o, out, tails);
}